// round 6
// baseline (speedup 1.0000x reference)
#include <cuda_runtime.h>
#include <cstdint>

#define N_NODES 50000
#define CH 64
#define SCAN_THREADS 1024

__device__ float4 g_agg4[N_NODES * (CH / 4)];
__device__ int g_ei_is64;
__device__ int g_cnt[N_NODES];        // per-dst edge count
__device__ int g_start[N_NODES];      // exclusive prefix of counts
__device__ int g_cursor[N_NODES];     // write cursors for permute
__device__ int g_sorted_src[800000 + 1024];  // src ids grouped by dst

// ---------------------------------------------------------------------------
// k0: zero counters + dtype detect
// ---------------------------------------------------------------------------
__global__ void zero_detect_kernel(const int* __restrict__ ei32) {
    int i = blockIdx.x * blockDim.x + threadIdx.x;
    if (i < N_NODES) g_cnt[i] = 0;
    if (i == 0) {
        int is64 = 1;
        #pragma unroll
        for (int k = 0; k < 64; k++) {
            if (ei32[2 * k + 1] != 0) { is64 = 0; break; }
        }
        g_ei_is64 = is64;
    }
}

__device__ __forceinline__ void load_edge(const void* ei_raw, int nE, int e,
                                          int& src, int& dst) {
    if (g_ei_is64) {
        const long long* ei = (const long long*)ei_raw;
        src = (int)ei[e];
        dst = (int)ei[nE + e];
    } else {
        const int* ei = (const int*)ei_raw;
        src = ei[e];
        dst = ei[nE + e];
    }
}

// ---------------------------------------------------------------------------
// k1: histogram of dst
// ---------------------------------------------------------------------------
__global__ void hist_kernel(const void* __restrict__ ei_raw, int nE) {
    int e = blockIdx.x * blockDim.x + threadIdx.x;
    if (e >= nE) return;
    int src, dst;
    load_edge(ei_raw, nE, e, src, dst);
    if ((unsigned)dst < N_NODES) atomicAdd(&g_cnt[dst], 1);
}

// ---------------------------------------------------------------------------
// k2: single-block exclusive scan of g_cnt -> g_start, copy to g_cursor
// ---------------------------------------------------------------------------
__global__ void __launch_bounds__(SCAN_THREADS) scan_kernel() {
    __shared__ int spart[SCAN_THREADS];
    const int CHUNK = (N_NODES + SCAN_THREADS - 1) / SCAN_THREADS;  // 49
    int t = threadIdx.x;
    int lo = t * CHUNK;
    int hi = min(lo + CHUNK, N_NODES);

    int s = 0;
    for (int i = lo; i < hi; i++) s += g_cnt[i];
    spart[t] = s;
    __syncthreads();

    // Hillis-Steele inclusive scan over 1024 partials
    for (int off = 1; off < SCAN_THREADS; off <<= 1) {
        int v = (t >= off) ? spart[t - off] : 0;
        __syncthreads();
        spart[t] += v;
        __syncthreads();
    }
    int excl = (t == 0) ? 0 : spart[t - 1];

    for (int i = lo; i < hi; i++) {
        int c = g_cnt[i];
        g_start[i] = excl;
        g_cursor[i] = excl;
        excl += c;
    }
}

// ---------------------------------------------------------------------------
// k3: permute src ids into dst-grouped order
// ---------------------------------------------------------------------------
__global__ void permute_kernel(const void* __restrict__ ei_raw, int nE) {
    int e = blockIdx.x * blockDim.x + threadIdx.x;
    if (e >= nE) return;
    int src, dst;
    load_edge(ei_raw, nE, e, src, dst);
    if ((unsigned)dst >= N_NODES || (unsigned)src >= N_NODES) return;
    int pos = atomicAdd(&g_cursor[dst], 1);
    g_sorted_src[pos] = src;
}

// ---------------------------------------------------------------------------
// k4: aggregate. 16-lane group per node; lane owns one float4 column.
// acc starts at x[node] (folds in the old init kernel). 2-way unroll for MLP.
// ---------------------------------------------------------------------------
__global__ void aggregate_kernel(const float4* __restrict__ x4) {
    int g = blockIdx.x * blockDim.x + threadIdx.x;
    int lane = g & 15;
    int node = g >> 4;
    if (node >= N_NODES) return;

    int s = g_start[node];
    int e = s + g_cnt[node];

    float4 acc = x4[node * 16 + lane];
    float4 acc2 = make_float4(0.f, 0.f, 0.f, 0.f);

    int i = s;
    for (; i + 1 < e; i += 2) {
        int s0 = g_sorted_src[i];
        int s1 = g_sorted_src[i + 1];
        float4 v0 = x4[s0 * 16 + lane];
        float4 v1 = x4[s1 * 16 + lane];
        acc.x += v0.x; acc.y += v0.y; acc.z += v0.z; acc.w += v0.w;
        acc2.x += v1.x; acc2.y += v1.y; acc2.z += v1.z; acc2.w += v1.w;
    }
    if (i < e) {
        int s0 = g_sorted_src[i];
        float4 v0 = x4[s0 * 16 + lane];
        acc.x += v0.x; acc.y += v0.y; acc.z += v0.z; acc.w += v0.w;
    }
    acc.x += acc2.x; acc.y += acc2.y; acc.z += acc2.z; acc.w += acc2.w;
    g_agg4[node * 16 + lane] = acc;
}

// ---------------------------------------------------------------------------
// k5: out = relu(h @ W^T + b). 128 rows/block, 128 threads, 8x8 reg tiles.
// ---------------------------------------------------------------------------
#define GROWS 128
#define GTHREADS 128
#define HT_STRIDE (GROWS + 8)
#define WT_STRIDE 72
#define SMEM_BYTES ((64 * HT_STRIDE + 64 * WT_STRIDE) * 4)

__global__ void __launch_bounds__(GTHREADS) gemm_relu_kernel(
    const float* __restrict__ W,
    const float* __restrict__ b,
    float* __restrict__ out)
{
    extern __shared__ float smem[];
    float* sHT = smem;
    float* sWT = smem + 64 * HT_STRIDE;

    int t = threadIdx.x;
    int r0 = blockIdx.x * GROWS;

    #pragma unroll
    for (int k = 0; k < 32; k++) {
        int idx = t + k * 128;
        int o = idx >> 6;
        int i = idx & 63;
        sWT[i * WT_STRIDE + o] = W[idx];
    }
    {
        int row = r0 + t;
        if (row < N_NODES) {
            #pragma unroll
            for (int j = 0; j < 16; j++) {
                float4 v = g_agg4[row * 16 + j];
                sHT[(j * 4 + 0) * HT_STRIDE + t] = v.x;
                sHT[(j * 4 + 1) * HT_STRIDE + t] = v.y;
                sHT[(j * 4 + 2) * HT_STRIDE + t] = v.z;
                sHT[(j * 4 + 3) * HT_STRIDE + t] = v.w;
            }
        } else {
            #pragma unroll
            for (int i = 0; i < 64; i++) sHT[i * HT_STRIDE + t] = 0.f;
        }
    }
    __syncthreads();

    int tr = t >> 3;
    int tc = t & 7;
    int rbase = tr * 8;
    int obase = tc * 8;

    float acc[8][8];
    #pragma unroll
    for (int r = 0; r < 8; r++)
        #pragma unroll
        for (int c = 0; c < 8; c++)
            acc[r][c] = b[obase + c];

    #pragma unroll 8
    for (int i = 0; i < 64; i++) {
        float4 h0 = *reinterpret_cast<const float4*>(&sHT[i * HT_STRIDE + rbase]);
        float4 h1 = *reinterpret_cast<const float4*>(&sHT[i * HT_STRIDE + rbase + 4]);
        float4 w0 = *reinterpret_cast<const float4*>(&sWT[i * WT_STRIDE + obase]);
        float4 w1 = *reinterpret_cast<const float4*>(&sWT[i * WT_STRIDE + obase + 4]);
        float hv[8] = {h0.x, h0.y, h0.z, h0.w, h1.x, h1.y, h1.z, h1.w};
        float wv[8] = {w0.x, w0.y, w0.z, w0.w, w1.x, w1.y, w1.z, w1.w};
        #pragma unroll
        for (int r = 0; r < 8; r++)
            #pragma unroll
            for (int c = 0; c < 8; c++)
                acc[r][c] += hv[r] * wv[c];
    }

    #pragma unroll
    for (int r = 0; r < 8; r++) {
        int row = r0 + rbase + r;
        if (row < N_NODES) {
            float4 v0, v1;
            v0.x = fmaxf(acc[r][0], 0.f); v0.y = fmaxf(acc[r][1], 0.f);
            v0.z = fmaxf(acc[r][2], 0.f); v0.w = fmaxf(acc[r][3], 0.f);
            v1.x = fmaxf(acc[r][4], 0.f); v1.y = fmaxf(acc[r][5], 0.f);
            v1.z = fmaxf(acc[r][6], 0.f); v1.w = fmaxf(acc[r][7], 0.f);
            float4* o4 = reinterpret_cast<float4*>(out + row * CH + obase);
            o4[0] = v0;
            o4[1] = v1;
        }
    }
}

// ---------------------------------------------------------------------------
extern "C" void kernel_launch(void* const* d_in, const int* in_sizes, int n_in,
                              void* d_out, int out_size) {
    const float* x  = (const float*)d_in[0];
    const void*  ei = d_in[1];
    const float* W  = (const float*)d_in[2];
    const float* b  = (const float*)d_in[3];
    float* out = (float*)d_out;

    int nE = in_sizes[1] / 2;                 // 800000

    static bool attr_done = false;
    if (!attr_done) {
        cudaFuncSetAttribute(gemm_relu_kernel,
                             cudaFuncAttributeMaxDynamicSharedMemorySize,
                             SMEM_BYTES);
        attr_done = true;
    }

    zero_detect_kernel<<<(N_NODES + 255) / 256, 256>>>((const int*)ei);
    hist_kernel<<<(nE + 255) / 256, 256>>>(ei, nE);
    scan_kernel<<<1, SCAN_THREADS>>>();
    permute_kernel<<<(nE + 255) / 256, 256>>>(ei, nE);

    long long athreads = (long long)N_NODES * 16;
    aggregate_kernel<<<(int)((athreads + 255) / 256), 256>>>(
        reinterpret_cast<const float4*>(x));

    int gblocks = (N_NODES + GROWS - 1) / GROWS;
    gemm_relu_kernel<<<gblocks, GTHREADS, SMEM_BYTES>>>(W, b, out);
}

// round 7
// speedup vs baseline: 1.8430x; 1.8430x over previous
#include <cuda_runtime.h>
#include <cstdint>

#define N_NODES 50000
#define CH 64

// sum-only accumulator (zeroed by memset; x added during GEMM staging)
__device__ float4 g_agg4[N_NODES * (CH / 4)];
// dtype flag for edge_index: 1 = int64, 0 = int32
__device__ int g_ei_is64;

// ---------------------------------------------------------------------------
// Kernel 0: edge-index dtype detection (tiny).
// int64 indices < 2^31 have every odd 32-bit word zero; 64 random int32
// node ids all being zero is impossible.
// ---------------------------------------------------------------------------
__global__ void detect_kernel(const int* __restrict__ ei32) {
    if (threadIdx.x == 0) {
        int is64 = 1;
        #pragma unroll
        for (int k = 0; k < 64; k++) {
            if (ei32[2 * k + 1] != 0) { is64 = 0; break; }
        }
        g_ei_is64 = is64;
    }
}

// ---------------------------------------------------------------------------
// Kernel 1: scatter-add. One 16-lane group per edge; lane owns one float4.
// red.global.add.v4.f32 = vectorized no-return reduction.
// ---------------------------------------------------------------------------
__global__ void scatter_kernel(const float4* __restrict__ x4,
                               const void* __restrict__ ei_raw,
                               int nE) {
    int g = blockIdx.x * blockDim.x + threadIdx.x;
    int lane = g & 15;
    int edge = g >> 4;
    if (edge >= nE) return;

    long long src, dst;
    if (g_ei_is64) {
        const long long* ei = (const long long*)ei_raw;
        src = ei[edge];
        dst = ei[nE + edge];
    } else {
        const int* ei = (const int*)ei_raw;
        src = ei[edge];
        dst = ei[nE + edge];
    }
    if ((unsigned long long)src >= N_NODES || (unsigned long long)dst >= N_NODES)
        return;

    float4 v = x4[src * 16 + lane];
    float4* dptr = g_agg4 + dst * 16 + lane;
    asm volatile("red.global.add.v4.f32 [%0], {%1, %2, %3, %4};"
                 :: "l"(dptr), "f"(v.x), "f"(v.y), "f"(v.z), "f"(v.w)
                 : "memory");
}

// ---------------------------------------------------------------------------
// Kernel 2: out = relu((x + agg) @ W^T + b).
// 128 rows/block, 128 threads, dynamic smem, 8x8 register tiles.
// h = x + agg computed during the k-major staging of sHT.
// ---------------------------------------------------------------------------
#define GROWS 128
#define GTHREADS 128
#define HT_STRIDE (GROWS + 8)
#define WT_STRIDE 72
#define SMEM_BYTES ((64 * HT_STRIDE + 64 * WT_STRIDE) * 4)

__global__ void __launch_bounds__(GTHREADS) gemm_relu_kernel(
    const float4* __restrict__ x4,
    const float* __restrict__ W,   // [64,64] row-major (o,i)
    const float* __restrict__ b,   // [64]
    float* __restrict__ out)       // [N,64]
{
    extern __shared__ float smem[];
    float* sHT = smem;                       // [64][HT_STRIDE]  (k-major)
    float* sWT = smem + 64 * HT_STRIDE;      // [64][WT_STRIDE]  (k-major)

    int t = threadIdx.x;
    int r0 = blockIdx.x * GROWS;

    #pragma unroll
    for (int k = 0; k < 32; k++) {
        int idx = t + k * 128;       // idx = o*64 + i
        int o = idx >> 6;
        int i = idx & 63;
        sWT[i * WT_STRIDE + o] = W[idx];
    }
    {
        int row = r0 + t;
        if (row < N_NODES) {
            #pragma unroll
            for (int j = 0; j < 16; j++) {
                float4 vx = x4[row * 16 + j];
                float4 va = g_agg4[row * 16 + j];
                sHT[(j * 4 + 0) * HT_STRIDE + t] = vx.x + va.x;
                sHT[(j * 4 + 1) * HT_STRIDE + t] = vx.y + va.y;
                sHT[(j * 4 + 2) * HT_STRIDE + t] = vx.z + va.z;
                sHT[(j * 4 + 3) * HT_STRIDE + t] = vx.w + va.w;
            }
        } else {
            #pragma unroll
            for (int i = 0; i < 64; i++) sHT[i * HT_STRIDE + t] = 0.f;
        }
    }
    __syncthreads();

    int tr = t >> 3;
    int tc = t & 7;
    int rbase = tr * 8;
    int obase = tc * 8;

    float acc[8][8];
    #pragma unroll
    for (int r = 0; r < 8; r++)
        #pragma unroll
        for (int c = 0; c < 8; c++)
            acc[r][c] = b[obase + c];

    #pragma unroll 8
    for (int i = 0; i < 64; i++) {
        float4 h0 = *reinterpret_cast<const float4*>(&sHT[i * HT_STRIDE + rbase]);
        float4 h1 = *reinterpret_cast<const float4*>(&sHT[i * HT_STRIDE + rbase + 4]);
        float4 w0 = *reinterpret_cast<const float4*>(&sWT[i * WT_STRIDE + obase]);
        float4 w1 = *reinterpret_cast<const float4*>(&sWT[i * WT_STRIDE + obase + 4]);
        float hv[8] = {h0.x, h0.y, h0.z, h0.w, h1.x, h1.y, h1.z, h1.w};
        float wv[8] = {w0.x, w0.y, w0.z, w0.w, w1.x, w1.y, w1.z, w1.w};
        #pragma unroll
        for (int r = 0; r < 8; r++)
            #pragma unroll
            for (int c = 0; c < 8; c++)
                acc[r][c] += hv[r] * wv[c];
    }

    #pragma unroll
    for (int r = 0; r < 8; r++) {
        int row = r0 + rbase + r;
        if (row < N_NODES) {
            float4 v0, v1;
            v0.x = fmaxf(acc[r][0], 0.f); v0.y = fmaxf(acc[r][1], 0.f);
            v0.z = fmaxf(acc[r][2], 0.f); v0.w = fmaxf(acc[r][3], 0.f);
            v1.x = fmaxf(acc[r][4], 0.f); v1.y = fmaxf(acc[r][5], 0.f);
            v1.z = fmaxf(acc[r][6], 0.f); v1.w = fmaxf(acc[r][7], 0.f);
            float4* o4 = reinterpret_cast<float4*>(out + row * CH + obase);
            o4[0] = v0;
            o4[1] = v1;
        }
    }
}

// ---------------------------------------------------------------------------
extern "C" void kernel_launch(void* const* d_in, const int* in_sizes, int n_in,
                              void* d_out, int out_size) {
    const float* x  = (const float*)d_in[0];
    const void*  ei = d_in[1];
    const float* W  = (const float*)d_in[2];
    const float* b  = (const float*)d_in[3];
    float* out = (float*)d_out;

    int nE = in_sizes[1] / 2;                 // 800000

    static bool attr_done = false;
    static void* agg_ptr = nullptr;
    if (!attr_done) {
        cudaFuncSetAttribute(gemm_relu_kernel,
                             cudaFuncAttributeMaxDynamicSharedMemorySize,
                             SMEM_BYTES);
        cudaGetSymbolAddress(&agg_ptr, g_agg4);
        attr_done = true;
    }

    detect_kernel<<<1, 32>>>((const int*)ei);

    // zero the sum accumulator (capturable memset node)
    cudaMemsetAsync(agg_ptr, 0, sizeof(float4) * N_NODES * (CH / 4));

    long long threads = (long long)nE * 16;
    int blocks = (int)((threads + 255) / 256);
    scatter_kernel<<<blocks, 256>>>(
        reinterpret_cast<const float4*>(x), ei, nE);

    int gblocks = (N_NODES + GROWS - 1) / GROWS;
    gemm_relu_kernel<<<gblocks, GTHREADS, SMEM_BYTES>>>(
        reinterpret_cast<const float4*>(x), W, b, out);
}

// round 8
// speedup vs baseline: 1.9353x; 1.0501x over previous
#include <cuda_runtime.h>
#include <cstdint>

#define N_NODES 50000
#define CH 64

// accumulator: initialized to x by init kernel, then scatter adds neighbors
__device__ float4 g_agg4[N_NODES * (CH / 4)];
// dtype flag for edge_index: 1 = int64, 0 = int32
__device__ int g_ei_is64;

// ---------------------------------------------------------------------------
// Kernel 1: agg = x (4 float4 per thread for MLP) + parallel dtype detect.
// int64 indices < 2^31 have every odd 32-bit word zero; 64 random int32
// node ids all being zero is impossible.
// ---------------------------------------------------------------------------
__global__ void init_agg_kernel(const float4* __restrict__ x4, int n4,
                                const int* __restrict__ ei32) {
    int base = (blockIdx.x * blockDim.x + threadIdx.x) * 4;
    if (base + 3 < n4) {
        float4 v0 = x4[base + 0];
        float4 v1 = x4[base + 1];
        float4 v2 = x4[base + 2];
        float4 v3 = x4[base + 3];
        g_agg4[base + 0] = v0;
        g_agg4[base + 1] = v1;
        g_agg4[base + 2] = v2;
        g_agg4[base + 3] = v3;
    } else {
        for (int i = base; i < n4; i++) g_agg4[i] = x4[i];
    }

    if (blockIdx.x == 0 && threadIdx.x < 32) {
        int lane = threadIdx.x;
        // lane k checks odd words of int64 candidates k and k+32
        int bad = (ei32[2 * lane + 1] != 0) | (ei32[2 * (lane + 32) + 1] != 0);
        unsigned m = __ballot_sync(0xFFFFFFFFu, bad);
        if (lane == 0) g_ei_is64 = (m == 0u) ? 1 : 0;
    }
}

// ---------------------------------------------------------------------------
// Kernel 2: scatter-add. One 16-lane group per edge; lane owns one float4.
// red.global.add.v4.f32 = vectorized no-return reduction.
// ---------------------------------------------------------------------------
__global__ void scatter_kernel(const float4* __restrict__ x4,
                               const void* __restrict__ ei_raw,
                               int nE) {
    int g = blockIdx.x * blockDim.x + threadIdx.x;
    int lane = g & 15;
    int edge = g >> 4;
    if (edge >= nE) return;

    long long src, dst;
    if (g_ei_is64) {
        const long long* ei = (const long long*)ei_raw;
        src = ei[edge];
        dst = ei[nE + edge];
    } else {
        const int* ei = (const int*)ei_raw;
        src = ei[edge];
        dst = ei[nE + edge];
    }
    if ((unsigned long long)src >= N_NODES || (unsigned long long)dst >= N_NODES)
        return;

    float4 v = x4[src * 16 + lane];
    float4* dptr = g_agg4 + dst * 16 + lane;
    asm volatile("red.global.add.v4.f32 [%0], {%1, %2, %3, %4};"
                 :: "l"(dptr), "f"(v.x), "f"(v.y), "f"(v.z), "f"(v.w)
                 : "memory");
}

// ---------------------------------------------------------------------------
// Kernel 3: out = relu(h @ W^T + b), h = g_agg (already x + sum).
// 128 rows/block, 128 threads, dynamic smem, 8x8 register tiles.
// ---------------------------------------------------------------------------
#define GROWS 128
#define GTHREADS 128
#define HT_STRIDE (GROWS + 8)
#define WT_STRIDE 72
#define SMEM_BYTES ((64 * HT_STRIDE + 64 * WT_STRIDE) * 4)

__global__ void __launch_bounds__(GTHREADS) gemm_relu_kernel(
    const float* __restrict__ W,   // [64,64] row-major (o,i)
    const float* __restrict__ b,   // [64]
    float* __restrict__ out)       // [N,64]
{
    extern __shared__ float smem[];
    float* sHT = smem;                       // [64][HT_STRIDE]  (k-major)
    float* sWT = smem + 64 * HT_STRIDE;      // [64][WT_STRIDE]  (k-major)

    int t = threadIdx.x;
    int r0 = blockIdx.x * GROWS;

    #pragma unroll
    for (int k = 0; k < 32; k++) {
        int idx = t + k * 128;       // idx = o*64 + i
        int o = idx >> 6;
        int i = idx & 63;
        sWT[i * WT_STRIDE + o] = W[idx];
    }
    {
        int row = r0 + t;
        if (row < N_NODES) {
            #pragma unroll
            for (int j = 0; j < 16; j++) {
                float4 v = g_agg4[row * 16 + j];
                sHT[(j * 4 + 0) * HT_STRIDE + t] = v.x;
                sHT[(j * 4 + 1) * HT_STRIDE + t] = v.y;
                sHT[(j * 4 + 2) * HT_STRIDE + t] = v.z;
                sHT[(j * 4 + 3) * HT_STRIDE + t] = v.w;
            }
        } else {
            #pragma unroll
            for (int i = 0; i < 64; i++) sHT[i * HT_STRIDE + t] = 0.f;
        }
    }
    __syncthreads();

    int tr = t >> 3;
    int tc = t & 7;
    int rbase = tr * 8;
    int obase = tc * 8;

    float acc[8][8];
    #pragma unroll
    for (int r = 0; r < 8; r++)
        #pragma unroll
        for (int c = 0; c < 8; c++)
            acc[r][c] = b[obase + c];

    #pragma unroll 8
    for (int i = 0; i < 64; i++) {
        float4 h0 = *reinterpret_cast<const float4*>(&sHT[i * HT_STRIDE + rbase]);
        float4 h1 = *reinterpret_cast<const float4*>(&sHT[i * HT_STRIDE + rbase + 4]);
        float4 w0 = *reinterpret_cast<const float4*>(&sWT[i * WT_STRIDE + obase]);
        float4 w1 = *reinterpret_cast<const float4*>(&sWT[i * WT_STRIDE + obase + 4]);
        float hv[8] = {h0.x, h0.y, h0.z, h0.w, h1.x, h1.y, h1.z, h1.w};
        float wv[8] = {w0.x, w0.y, w0.z, w0.w, w1.x, w1.y, w1.z, w1.w};
        #pragma unroll
        for (int r = 0; r < 8; r++)
            #pragma unroll
            for (int c = 0; c < 8; c++)
                acc[r][c] += hv[r] * wv[c];
    }

    #pragma unroll
    for (int r = 0; r < 8; r++) {
        int row = r0 + rbase + r;
        if (row < N_NODES) {
            float4 v0, v1;
            v0.x = fmaxf(acc[r][0], 0.f); v0.y = fmaxf(acc[r][1], 0.f);
            v0.z = fmaxf(acc[r][2], 0.f); v0.w = fmaxf(acc[r][3], 0.f);
            v1.x = fmaxf(acc[r][4], 0.f); v1.y = fmaxf(acc[r][5], 0.f);
            v1.z = fmaxf(acc[r][6], 0.f); v1.w = fmaxf(acc[r][7], 0.f);
            float4* o4 = reinterpret_cast<float4*>(out + row * CH + obase);
            o4[0] = v0;
            o4[1] = v1;
        }
    }
}

// ---------------------------------------------------------------------------
extern "C" void kernel_launch(void* const* d_in, const int* in_sizes, int n_in,
                              void* d_out, int out_size) {
    const float* x  = (const float*)d_in[0];
    const void*  ei = d_in[1];
    const float* W  = (const float*)d_in[2];
    const float* b  = (const float*)d_in[3];
    float* out = (float*)d_out;

    int nE = in_sizes[1] / 2;                 // 800000
    int n4 = (N_NODES * CH) / 4;              // 800000 float4

    static bool attr_done = false;
    if (!attr_done) {
        cudaFuncSetAttribute(gemm_relu_kernel,
                             cudaFuncAttributeMaxDynamicSharedMemorySize,
                             SMEM_BYTES);
        attr_done = true;
    }

    // init: 4 float4 per thread
    int ithreads = (n4 + 3) / 4;
    init_agg_kernel<<<(ithreads + 255) / 256, 256>>>(
        reinterpret_cast<const float4*>(x), n4, (const int*)ei);

    long long threads = (long long)nE * 16;
    int blocks = (int)((threads + 255) / 256);
    scatter_kernel<<<blocks, 256>>>(
        reinterpret_cast<const float4*>(x), ei, nE);

    int gblocks = (N_NODES + GROWS - 1) / GROWS;
    gemm_relu_kernel<<<gblocks, GTHREADS, SMEM_BYTES>>>(W, b, out);
}

// round 9
// speedup vs baseline: 2.1215x; 1.0962x over previous
#include <cuda_runtime.h>
#include <cstdint>

#define N_NODES 50000
#define CH 64

// accumulator: initialized to x by init kernel, then scatter adds neighbors
__device__ float4 g_agg4[N_NODES * (CH / 4)];
// dtype flag for edge_index: 1 = int64, 0 = int32
__device__ int g_ei_is64;

// ---------------------------------------------------------------------------
// Kernel 1: agg = x. Interleaved 2 float4/thread (independent pairs, MLP=2)
// + parallel ballot dtype detect in block 0.
// ---------------------------------------------------------------------------
__global__ void init_agg_kernel(const float4* __restrict__ x4, int n4,
                                const int* __restrict__ ei32) {
    int stride = gridDim.x * blockDim.x;
    int i = blockIdx.x * blockDim.x + threadIdx.x;
    int i2 = i + stride;
    if (i < n4) {
        float4 v0 = x4[i];
        float4 v1 = (i2 < n4) ? x4[i2] : make_float4(0.f, 0.f, 0.f, 0.f);
        g_agg4[i] = v0;
        if (i2 < n4) g_agg4[i2] = v1;
    }

    if (blockIdx.x == 0 && threadIdx.x < 32) {
        int lane = threadIdx.x;
        // lane k checks odd words of int64 candidates k and k+32
        int bad = (ei32[2 * lane + 1] != 0) | (ei32[2 * (lane + 32) + 1] != 0);
        unsigned m = __ballot_sync(0xFFFFFFFFu, bad);
        if (lane == 0) g_ei_is64 = (m == 0u) ? 1 : 0;
    }
}

// ---------------------------------------------------------------------------
// Kernel 2: scatter-add. 8-lane group per edge; lane owns float4 j and j+8.
// 2 independent gathers + 2 RED.v4 per thread (MLP=2).
// ---------------------------------------------------------------------------
__global__ void scatter_kernel(const float4* __restrict__ x4,
                               const void* __restrict__ ei_raw,
                               int nE) {
    int g = blockIdx.x * blockDim.x + threadIdx.x;
    int lane = g & 7;
    int edge = g >> 3;
    if (edge >= nE) return;

    long long src, dst;
    if (g_ei_is64) {
        const long long* ei = (const long long*)ei_raw;
        src = ei[edge];
        dst = ei[nE + edge];
    } else {
        const int* ei = (const int*)ei_raw;
        src = ei[edge];
        dst = ei[nE + edge];
    }
    if ((unsigned long long)src >= N_NODES || (unsigned long long)dst >= N_NODES)
        return;

    float4 v0 = x4[src * 16 + lane];
    float4 v1 = x4[src * 16 + lane + 8];
    float4* d0 = g_agg4 + dst * 16 + lane;
    float4* d1 = g_agg4 + dst * 16 + lane + 8;
    asm volatile("red.global.add.v4.f32 [%0], {%1, %2, %3, %4};"
                 :: "l"(d0), "f"(v0.x), "f"(v0.y), "f"(v0.z), "f"(v0.w)
                 : "memory");
    asm volatile("red.global.add.v4.f32 [%0], {%1, %2, %3, %4};"
                 :: "l"(d1), "f"(v1.x), "f"(v1.y), "f"(v1.z), "f"(v1.w)
                 : "memory");
}

// ---------------------------------------------------------------------------
// Kernel 3: out = relu(h @ W^T + b), h = g_agg (already x + sum).
// 128 rows/block, 128 threads, dynamic smem, 8x8 register tiles.
// ---------------------------------------------------------------------------
#define GROWS 128
#define GTHREADS 128
#define HT_STRIDE (GROWS + 8)
#define WT_STRIDE 72
#define SMEM_BYTES ((64 * HT_STRIDE + 64 * WT_STRIDE) * 4)

__global__ void __launch_bounds__(GTHREADS) gemm_relu_kernel(
    const float* __restrict__ W,   // [64,64] row-major (o,i)
    const float* __restrict__ b,   // [64]
    float* __restrict__ out)       // [N,64]
{
    extern __shared__ float smem[];
    float* sHT = smem;                       // [64][HT_STRIDE]  (k-major)
    float* sWT = smem + 64 * HT_STRIDE;      // [64][WT_STRIDE]  (k-major)

    int t = threadIdx.x;
    int r0 = blockIdx.x * GROWS;

    #pragma unroll
    for (int k = 0; k < 32; k++) {
        int idx = t + k * 128;       // idx = o*64 + i
        int o = idx >> 6;
        int i = idx & 63;
        sWT[i * WT_STRIDE + o] = W[idx];
    }
    {
        int row = r0 + t;
        if (row < N_NODES) {
            #pragma unroll
            for (int j = 0; j < 16; j++) {
                float4 v = g_agg4[row * 16 + j];
                sHT[(j * 4 + 0) * HT_STRIDE + t] = v.x;
                sHT[(j * 4 + 1) * HT_STRIDE + t] = v.y;
                sHT[(j * 4 + 2) * HT_STRIDE + t] = v.z;
                sHT[(j * 4 + 3) * HT_STRIDE + t] = v.w;
            }
        } else {
            #pragma unroll
            for (int i = 0; i < 64; i++) sHT[i * HT_STRIDE + t] = 0.f;
        }
    }
    __syncthreads();

    int tr = t >> 3;
    int tc = t & 7;
    int rbase = tr * 8;
    int obase = tc * 8;

    float acc[8][8];
    #pragma unroll
    for (int r = 0; r < 8; r++)
        #pragma unroll
        for (int c = 0; c < 8; c++)
            acc[r][c] = b[obase + c];

    #pragma unroll 8
    for (int i = 0; i < 64; i++) {
        float4 h0 = *reinterpret_cast<const float4*>(&sHT[i * HT_STRIDE + rbase]);
        float4 h1 = *reinterpret_cast<const float4*>(&sHT[i * HT_STRIDE + rbase + 4]);
        float4 w0 = *reinterpret_cast<const float4*>(&sWT[i * WT_STRIDE + obase]);
        float4 w1 = *reinterpret_cast<const float4*>(&sWT[i * WT_STRIDE + obase + 4]);
        float hv[8] = {h0.x, h0.y, h0.z, h0.w, h1.x, h1.y, h1.z, h1.w};
        float wv[8] = {w0.x, w0.y, w0.z, w0.w, w1.x, w1.y, w1.z, w1.w};
        #pragma unroll
        for (int r = 0; r < 8; r++)
            #pragma unroll
            for (int c = 0; c < 8; c++)
                acc[r][c] += hv[r] * wv[c];
    }

    #pragma unroll
    for (int r = 0; r < 8; r++) {
        int row = r0 + rbase + r;
        if (row < N_NODES) {
            float4 v0, v1;
            v0.x = fmaxf(acc[r][0], 0.f); v0.y = fmaxf(acc[r][1], 0.f);
            v0.z = fmaxf(acc[r][2], 0.f); v0.w = fmaxf(acc[r][3], 0.f);
            v1.x = fmaxf(acc[r][4], 0.f); v1.y = fmaxf(acc[r][5], 0.f);
            v1.z = fmaxf(acc[r][6], 0.f); v1.w = fmaxf(acc[r][7], 0.f);
            float4* o4 = reinterpret_cast<float4*>(out + row * CH + obase);
            o4[0] = v0;
            o4[1] = v1;
        }
    }
}

// ---------------------------------------------------------------------------
extern "C" void kernel_launch(void* const* d_in, const int* in_sizes, int n_in,
                              void* d_out, int out_size) {
    const float* x  = (const float*)d_in[0];
    const void*  ei = d_in[1];
    const float* W  = (const float*)d_in[2];
    const float* b  = (const float*)d_in[3];
    float* out = (float*)d_out;

    int nE = in_sizes[1] / 2;                 // 800000
    int n4 = (N_NODES * CH) / 4;              // 800000 float4

    static bool attr_done = false;
    if (!attr_done) {
        cudaFuncSetAttribute(gemm_relu_kernel,
                             cudaFuncAttributeMaxDynamicSharedMemorySize,
                             SMEM_BYTES);
        attr_done = true;
    }

    // init: 2 interleaved float4 per thread
    int ithreads = (n4 + 1) / 2;
    init_agg_kernel<<<(ithreads + 255) / 256, 256>>>(
        reinterpret_cast<const float4*>(x), n4, (const int*)ei);

    long long threads = (long long)nE * 8;
    int blocks = (int)((threads + 255) / 256);
    scatter_kernel<<<blocks, 256>>>(
        reinterpret_cast<const float4*>(x), ei, nE);

    int gblocks = (N_NODES + GROWS - 1) / GROWS;
    gemm_relu_kernel<<<gblocks, GTHREADS, SMEM_BYTES>>>(W, b, out);
}

// round 10
// speedup vs baseline: 2.1318x; 1.0049x over previous
#include <cuda_runtime.h>
#include <cstdint>

#define N_NODES 50000
#define CH 64

// accumulator: initialized to x by init kernel, then scatter adds neighbors
__device__ float4 g_agg4[N_NODES * (CH / 4)];
// dtype flag for edge_index: 1 = int64, 0 = int32
__device__ int g_ei_is64;

// ---------------------------------------------------------------------------
// Kernel 1: agg = x. Interleaved 2 float4/thread (independent pairs, MLP=2)
// + parallel ballot dtype detect in block 0.
// ---------------------------------------------------------------------------
__global__ void init_agg_kernel(const float4* __restrict__ x4, int n4,
                                const int* __restrict__ ei32) {
    int stride = gridDim.x * blockDim.x;
    int i = blockIdx.x * blockDim.x + threadIdx.x;
    int i2 = i + stride;
    if (i < n4) {
        float4 v0 = x4[i];
        float4 v1 = (i2 < n4) ? x4[i2] : make_float4(0.f, 0.f, 0.f, 0.f);
        g_agg4[i] = v0;
        if (i2 < n4) g_agg4[i2] = v1;
    }

    if (blockIdx.x == 0 && threadIdx.x < 32) {
        int lane = threadIdx.x;
        int bad = (ei32[2 * lane + 1] != 0) | (ei32[2 * (lane + 32) + 1] != 0);
        unsigned m = __ballot_sync(0xFFFFFFFFu, bad);
        if (lane == 0) g_ei_is64 = (m == 0u) ? 1 : 0;
    }
}

// ---------------------------------------------------------------------------
// Kernel 2: scatter-add. 8-lane group per edge; lane owns float4 j and j+8.
// ---------------------------------------------------------------------------
__global__ void scatter_kernel(const float4* __restrict__ x4,
                               const void* __restrict__ ei_raw,
                               int nE) {
    int g = blockIdx.x * blockDim.x + threadIdx.x;
    int lane = g & 7;
    int edge = g >> 3;
    if (edge >= nE) return;

    long long src, dst;
    if (g_ei_is64) {
        const long long* ei = (const long long*)ei_raw;
        src = ei[edge];
        dst = ei[nE + edge];
    } else {
        const int* ei = (const int*)ei_raw;
        src = ei[edge];
        dst = ei[nE + edge];
    }
    if ((unsigned long long)src >= N_NODES || (unsigned long long)dst >= N_NODES)
        return;

    float4 v0 = x4[src * 16 + lane];
    float4 v1 = x4[src * 16 + lane + 8];
    float4* d0 = g_agg4 + dst * 16 + lane;
    float4* d1 = g_agg4 + dst * 16 + lane + 8;
    asm volatile("red.global.add.v4.f32 [%0], {%1, %2, %3, %4};"
                 :: "l"(d0), "f"(v0.x), "f"(v0.y), "f"(v0.z), "f"(v0.w)
                 : "memory");
    asm volatile("red.global.add.v4.f32 [%0], {%1, %2, %3, %4};"
                 :: "l"(d1), "f"(v1.x), "f"(v1.y), "f"(v1.z), "f"(v1.w)
                 : "memory");
}

// ---------------------------------------------------------------------------
// Kernel 3: out = relu(h @ W^T + b) using packed fma.rn.f32x2 (FFMA2).
// Same staging as before; acc = 8 rows x 4 column-pairs (64-bit each).
// Column pairs come free from the float4 sWT loads; h splatted via mov.b64.
// ---------------------------------------------------------------------------
#define GROWS 128
#define GTHREADS 128
#define HT_STRIDE (GROWS + 8)
#define WT_STRIDE 72
#define SMEM_BYTES ((64 * HT_STRIDE + 64 * WT_STRIDE) * 4)

__device__ __forceinline__ unsigned long long splat_f32x2(float v) {
    unsigned long long d;
    unsigned u = __float_as_uint(v);
    asm("mov.b64 %0, {%1, %1};" : "=l"(d) : "r"(u));
    return d;
}
__device__ __forceinline__ unsigned long long pack_f32x2(float lo, float hi) {
    unsigned long long d;
    asm("mov.b64 %0, {%1, %2};" : "=l"(d) : "r"(__float_as_uint(lo)), "r"(__float_as_uint(hi)));
    return d;
}
#define FFMA2(acc, a, b) \
    asm("fma.rn.f32x2 %0, %1, %2, %0;" : "+l"(acc) : "l"(a), "l"(b))

__global__ void __launch_bounds__(GTHREADS) gemm_relu_kernel(
    const float* __restrict__ W,   // [64,64] row-major (o,i)
    const float* __restrict__ b,   // [64]
    float* __restrict__ out)       // [N,64]
{
    extern __shared__ float smem[];
    float* sHT = smem;                       // [64][HT_STRIDE]  (k-major)
    float* sWT = smem + 64 * HT_STRIDE;      // [64][WT_STRIDE]  (k-major)

    int t = threadIdx.x;
    int r0 = blockIdx.x * GROWS;

    #pragma unroll
    for (int k = 0; k < 32; k++) {
        int idx = t + k * 128;       // idx = o*64 + i
        int o = idx >> 6;
        int i = idx & 63;
        sWT[i * WT_STRIDE + o] = W[idx];
    }
    {
        int row = r0 + t;
        if (row < N_NODES) {
            #pragma unroll
            for (int j = 0; j < 16; j++) {
                float4 v = g_agg4[row * 16 + j];
                sHT[(j * 4 + 0) * HT_STRIDE + t] = v.x;
                sHT[(j * 4 + 1) * HT_STRIDE + t] = v.y;
                sHT[(j * 4 + 2) * HT_STRIDE + t] = v.z;
                sHT[(j * 4 + 3) * HT_STRIDE + t] = v.w;
            }
        } else {
            #pragma unroll
            for (int i = 0; i < 64; i++) sHT[i * HT_STRIDE + t] = 0.f;
        }
    }
    __syncthreads();

    int tr = t >> 3;
    int tc = t & 7;
    int rbase = tr * 8;
    int obase = tc * 8;

    // acc[r][cp]: row r, column pair (obase+2cp, obase+2cp+1)
    unsigned long long acc[8][4];
    {
        unsigned long long bp[4];
        #pragma unroll
        for (int cp = 0; cp < 4; cp++)
            bp[cp] = pack_f32x2(b[obase + 2 * cp], b[obase + 2 * cp + 1]);
        #pragma unroll
        for (int r = 0; r < 8; r++)
            #pragma unroll
            for (int cp = 0; cp < 4; cp++)
                acc[r][cp] = bp[cp];
    }

    #pragma unroll 8
    for (int i = 0; i < 64; i++) {
        float4 h0 = *reinterpret_cast<const float4*>(&sHT[i * HT_STRIDE + rbase]);
        float4 h1 = *reinterpret_cast<const float4*>(&sHT[i * HT_STRIDE + rbase + 4]);
        // w pairs: lo = even column (little-endian order of float4 lanes)
        ulonglong2 wA = *reinterpret_cast<const ulonglong2*>(&sWT[i * WT_STRIDE + obase]);
        ulonglong2 wB = *reinterpret_cast<const ulonglong2*>(&sWT[i * WT_STRIDE + obase + 4]);
        unsigned long long wp[4] = {wA.x, wA.y, wB.x, wB.y};
        float hv[8] = {h0.x, h0.y, h0.z, h0.w, h1.x, h1.y, h1.z, h1.w};
        #pragma unroll
        for (int r = 0; r < 8; r++) {
            unsigned long long h2 = splat_f32x2(hv[r]);
            #pragma unroll
            for (int cp = 0; cp < 4; cp++)
                FFMA2(acc[r][cp], h2, wp[cp]);
        }
    }

    #pragma unroll
    for (int r = 0; r < 8; r++) {
        int row = r0 + rbase + r;
        if (row < N_NODES) {
            float v[8];
            #pragma unroll
            for (int cp = 0; cp < 4; cp++) {
                float2 f = *reinterpret_cast<float2*>(&acc[r][cp]);
                v[2 * cp]     = fmaxf(f.x, 0.f);
                v[2 * cp + 1] = fmaxf(f.y, 0.f);
            }
            float4* o4 = reinterpret_cast<float4*>(out + row * CH + obase);
            o4[0] = make_float4(v[0], v[1], v[2], v[3]);
            o4[1] = make_float4(v[4], v[5], v[6], v[7]);
        }
    }
}

// ---------------------------------------------------------------------------
extern "C" void kernel_launch(void* const* d_in, const int* in_sizes, int n_in,
                              void* d_out, int out_size) {
    const float* x  = (const float*)d_in[0];
    const void*  ei = d_in[1];
    const float* W  = (const float*)d_in[2];
    const float* b  = (const float*)d_in[3];
    float* out = (float*)d_out;

    int nE = in_sizes[1] / 2;                 // 800000
    int n4 = (N_NODES * CH) / 4;              // 800000 float4

    static bool attr_done = false;
    if (!attr_done) {
        cudaFuncSetAttribute(gemm_relu_kernel,
                             cudaFuncAttributeMaxDynamicSharedMemorySize,
                             SMEM_BYTES);
        attr_done = true;
    }

    int ithreads = (n4 + 1) / 2;
    init_agg_kernel<<<(ithreads + 255) / 256, 256>>>(
        reinterpret_cast<const float4*>(x), n4, (const int*)ei);

    long long threads = (long long)nE * 8;
    int blocks = (int)((threads + 255) / 256);
    scatter_kernel<<<blocks, 256>>>(
        reinterpret_cast<const float4*>(x), ei, nE);

    int gblocks = (N_NODES + GROWS - 1) / GROWS;
    gemm_relu_kernel<<<gblocks, GTHREADS, SMEM_BYTES>>>(W, b, out);
}

// round 11
// speedup vs baseline: 2.2219x; 1.0422x over previous
#include <cuda_runtime.h>
#include <cstdint>

#define N_NODES 50000
#define CH 64

__device__ float4 g_agg4[N_NODES * (CH / 4)];
__device__ int g_ei_is64;

// ---------------------------------------------------------------------------
// Kernel 1: agg = x (interleaved 2 float4/thread) + ballot dtype detect.
// ---------------------------------------------------------------------------
__global__ void init_agg_kernel(const float4* __restrict__ x4, int n4,
                                const int* __restrict__ ei32) {
    int stride = gridDim.x * blockDim.x;
    int i = blockIdx.x * blockDim.x + threadIdx.x;
    int i2 = i + stride;
    if (i < n4) {
        float4 v0 = x4[i];
        float4 v1 = (i2 < n4) ? x4[i2] : make_float4(0.f, 0.f, 0.f, 0.f);
        g_agg4[i] = v0;
        if (i2 < n4) g_agg4[i2] = v1;
    }
    if (blockIdx.x == 0 && threadIdx.x < 32) {
        int lane = threadIdx.x;
        int bad = (ei32[2 * lane + 1] != 0) | (ei32[2 * (lane + 32) + 1] != 0);
        unsigned m = __ballot_sync(0xFFFFFFFFu, bad);
        if (lane == 0) g_ei_is64 = (m == 0u) ? 1 : 0;
    }
}

// ---------------------------------------------------------------------------
// Kernel 2: scatter-add. 8-lane group per edge; lane owns float4 j and j+8.
// ---------------------------------------------------------------------------
__global__ void scatter_kernel(const float4* __restrict__ x4,
                               const void* __restrict__ ei_raw,
                               int nE) {
    int g = blockIdx.x * blockDim.x + threadIdx.x;
    int lane = g & 7;
    int edge = g >> 3;
    if (edge >= nE) return;

    long long src, dst;
    if (g_ei_is64) {
        const long long* ei = (const long long*)ei_raw;
        src = ei[edge];
        dst = ei[nE + edge];
    } else {
        const int* ei = (const int*)ei_raw;
        src = ei[edge];
        dst = ei[nE + edge];
    }
    if ((unsigned long long)src >= N_NODES || (unsigned long long)dst >= N_NODES)
        return;

    float4 v0 = x4[src * 16 + lane];
    float4 v1 = x4[src * 16 + lane + 8];
    float4* d0 = g_agg4 + dst * 16 + lane;
    float4* d1 = g_agg4 + dst * 16 + lane + 8;
    asm volatile("red.global.add.v4.f32 [%0], {%1, %2, %3, %4};"
                 :: "l"(d0), "f"(v0.x), "f"(v0.y), "f"(v0.z), "f"(v0.w)
                 : "memory");
    asm volatile("red.global.add.v4.f32 [%0], {%1, %2, %3, %4};"
                 :: "l"(d1), "f"(v1.x), "f"(v1.y), "f"(v1.z), "f"(v1.w)
                 : "memory");
}

// ---------------------------------------------------------------------------
// Kernel 3: out = relu(h @ W^T + b).
// h staged COALESCED into row-major sH (float4 granularity) with XOR swizzle
// c4 ^= (row>>3)&15 for conflict-free compute reads. W k-major as before.
// Inner loop: per k-quad, 8 row-float4 LDS + per-k packed FFMA2.
// ---------------------------------------------------------------------------
#define GROWS 128
#define GTHREADS 128
#define H_STRIDE4 17                         // float4 stride per row
#define WT_STRIDE 72
#define SMEM_BYTES ((GROWS * H_STRIDE4 * 4 + 64 * WT_STRIDE) * 4)

__device__ __forceinline__ unsigned long long splat_f32x2(float v) {
    unsigned long long d;
    unsigned u = __float_as_uint(v);
    asm("mov.b64 %0, {%1, %1};" : "=l"(d) : "r"(u));
    return d;
}
__device__ __forceinline__ unsigned long long pack_f32x2(float lo, float hi) {
    unsigned long long d;
    asm("mov.b64 %0, {%1, %2};" : "=l"(d) : "r"(__float_as_uint(lo)), "r"(__float_as_uint(hi)));
    return d;
}
#define FFMA2(acc, a, b) \
    asm("fma.rn.f32x2 %0, %1, %2, %0;" : "+l"(acc) : "l"(a), "l"(b))

__global__ void __launch_bounds__(GTHREADS) gemm_relu_kernel(
    const float* __restrict__ W,   // [64,64] row-major (o,i)
    const float* __restrict__ b,   // [64]
    float* __restrict__ out)       // [N,64]
{
    extern __shared__ float smem[];
    float4* sH4 = reinterpret_cast<float4*>(smem);            // [128][17] f4, swizzled
    float*  sWT = smem + GROWS * H_STRIDE4 * 4;               // [64][72] k-major

    int t = threadIdx.x;
    int r0 = blockIdx.x * GROWS;

    // Stage W transposed (k-major)
    #pragma unroll
    for (int k = 0; k < 32; k++) {
        int idx = t + k * 128;       // idx = o*64 + i
        int o = idx >> 6;
        int i = idx & 63;
        sWT[i * WT_STRIDE + o] = W[idx];
    }
    // Stage h coalesced: idx = t + k*128 -> (row, c4); swizzled store
    #pragma unroll
    for (int k = 0; k < 16; k++) {
        int idx = t + k * 128;               // 0..2047
        int row = idx >> 4;
        int c4  = idx & 15;
        int grow = r0 + row;
        float4 v = (grow < N_NODES) ? g_agg4[grow * 16 + c4]
                                    : make_float4(0.f, 0.f, 0.f, 0.f);
        int c4s = c4 ^ ((row >> 3) & 15);
        sH4[row * H_STRIDE4 + c4s] = v;
    }
    __syncthreads();

    int tr = t >> 3;         // 0..15 row group
    int tc = t & 7;          // 0..7 col group
    int rbase = tr * 8;
    int obase = tc * 8;

    unsigned long long acc[8][4];
    {
        unsigned long long bp[4];
        #pragma unroll
        for (int cp = 0; cp < 4; cp++)
            bp[cp] = pack_f32x2(b[obase + 2 * cp], b[obase + 2 * cp + 1]);
        #pragma unroll
        for (int r = 0; r < 8; r++)
            #pragma unroll
            for (int cp = 0; cp < 4; cp++)
                acc[r][cp] = bp[cp];
    }

    #pragma unroll 4
    for (int q = 0; q < 16; q++) {           // i = 4q .. 4q+3
        float4 hr[8];
        int qs = q ^ tr;                     // swizzled column (row>>3 == tr for our rows)
        #pragma unroll
        for (int r = 0; r < 8; r++)
            hr[r] = sH4[(rbase + r) * H_STRIDE4 + qs];
        #pragma unroll
        for (int kk = 0; kk < 4; kk++) {
            int i = 4 * q + kk;
            ulonglong2 wA = *reinterpret_cast<const ulonglong2*>(&sWT[i * WT_STRIDE + obase]);
            ulonglong2 wB = *reinterpret_cast<const ulonglong2*>(&sWT[i * WT_STRIDE + obase + 4]);
            unsigned long long wp[4] = {wA.x, wA.y, wB.x, wB.y};
            #pragma unroll
            for (int r = 0; r < 8; r++) {
                float hv = (kk == 0) ? hr[r].x : (kk == 1) ? hr[r].y
                         : (kk == 2) ? hr[r].z : hr[r].w;
                unsigned long long h2 = splat_f32x2(hv);
                #pragma unroll
                for (int cp = 0; cp < 4; cp++)
                    FFMA2(acc[r][cp], h2, wp[cp]);
            }
        }
    }

    #pragma unroll
    for (int r = 0; r < 8; r++) {
        int row = r0 + rbase + r;
        if (row < N_NODES) {
            float v[8];
            #pragma unroll
            for (int cp = 0; cp < 4; cp++) {
                float2 f = *reinterpret_cast<float2*>(&acc[r][cp]);
                v[2 * cp]     = fmaxf(f.x, 0.f);
                v[2 * cp + 1] = fmaxf(f.y, 0.f);
            }
            float4* o4 = reinterpret_cast<float4*>(out + row * CH + obase);
            o4[0] = make_float4(v[0], v[1], v[2], v[3]);
            o4[1] = make_float4(v[4], v[5], v[6], v[7]);
        }
    }
}

// ---------------------------------------------------------------------------
extern "C" void kernel_launch(void* const* d_in, const int* in_sizes, int n_in,
                              void* d_out, int out_size) {
    const float* x  = (const float*)d_in[0];
    const void*  ei = d_in[1];
    const float* W  = (const float*)d_in[2];
    const float* b  = (const float*)d_in[3];
    float* out = (float*)d_out;

    int nE = in_sizes[1] / 2;                 // 800000
    int n4 = (N_NODES * CH) / 4;              // 800000 float4

    static bool attr_done = false;
    if (!attr_done) {
        cudaFuncSetAttribute(gemm_relu_kernel,
                             cudaFuncAttributeMaxDynamicSharedMemorySize,
                             SMEM_BYTES);
        attr_done = true;
    }

    int ithreads = (n4 + 1) / 2;
    init_agg_kernel<<<(ithreads + 255) / 256, 256>>>(
        reinterpret_cast<const float4*>(x), n4, (const int*)ei);

    long long threads = (long long)nE * 8;
    int blocks = (int)((threads + 255) / 256);
    scatter_kernel<<<blocks, 256>>>(
        reinterpret_cast<const float4*>(x), ei, nE);

    int gblocks = (N_NODES + GROWS - 1) / GROWS;
    gemm_relu_kernel<<<gblocks, GTHREADS, SMEM_BYTES>>>(W, b, out);
}